// round 10
// baseline (speedup 1.0000x reference)
#include <cuda_runtime.h>
#include <math.h>

// Problem constants (fixed by the dataset)
#define N_NODES 3072
#define IN_DIM  512
#define HD      512      // H*D
#define D       64
#define E_EDGES 98304
#define COL0    448      // start column of head 7 in the H*D projection
#define DEG_CAP 128      // fixed-stride adjacency slot count (Poisson(32): max~64)
#define KSPLIT  4        // split-K factor for proj

// mega grid layout (order matters for the spin-flag dependencies)
#define CS_BLOCKS   192              // colsum partials, 16 rows each
#define FILL_BLOCKS 384              // 384*256 = E exactly
#define PROJ_BLOCKS 576              // KSPLIT x 3 mats x 48 row-tiles (z-major)
#define MV_BLOCKS   16               // 32 cols each
#define CS_BASE     0
#define FILL_BASE   (CS_BASE + CS_BLOCKS)
#define PROJ_BASE   (FILL_BASE + FILL_BLOCKS)
#define MV_BASE     (PROJ_BASE + PROJ_BLOCKS)
#define MEGA_BLOCKS (MV_BASE + MV_BLOCKS)
#define N_TILES     144              // 3 mats x 48 row-tiles

// ---------------- scratch (device globals: allocation-free, zero-init) -----
__device__ float g_q7[N_NODES * D];        // raw x@Wq[:,448:512] (no bias)
__device__ float g_k7[N_NODES * D];
__device__ float g_v7[N_NODES * D];
__device__ int   g_cnt[N_NODES];           // self-cleaned by node_kernel
__device__ int   g_edst[N_NODES * DEG_CAP];
__device__ float g_xsump[CS_BLOCKS * IN_DIM];  // colsum partials (plain stores)
__device__ float g_mv[HD];                 // xsum . Wv[:,j] (plain stores)
__device__ int   g_tile_flag[N_TILES];     // z0-slice-done flags (self-cleaned)
__device__ int   g_cs_done;                // colsum-done counter (self-cleaned)

// ---------------- K1: mega kernel (colsum + fill + proj + mv) --------------
__global__ void __launch_bounds__(256)
mega_kernel(const float* __restrict__ x,
            const int*   __restrict__ ei32,
            const float* __restrict__ Wq,
            const float* __restrict__ Wk,
            const float* __restrict__ Wv) {
    int bid = blockIdx.x;
    int tid = threadIdx.x;

    if (bid < FILL_BASE) {
        // ---- colsum partials: 192 blocks x 16 rows, plain stores ----------
        int r0 = bid * 16;
        float s0 = 0.f, s1 = 0.f;
#pragma unroll
        for (int r = 0; r < 16; r++) {
            s0 += x[(r0 + r) * IN_DIM + tid];
            s1 += x[(r0 + r) * IN_DIM + tid + 256];
        }
        g_xsump[bid * IN_DIM + tid]       = s0;
        g_xsump[bid * IN_DIM + tid + 256] = s1;
        __syncthreads();
        __threadfence();
        if (tid == 0) atomicAdd(&g_cs_done, 1);
    } else if (bid < PROJ_BASE) {
        // ---- edge fill with per-block dtype sniff -------------------------
        // int64 layout => odd int32 words are high halves of ids < 3072 => 0.
        // int32 layout => odd words are random node ids (P(all 0) ~ 3072^-128).
        int flag = (tid < 128) ? ei32[2 * tid + 1] : 0;
        int any  = __syncthreads_or(flag);
        int is64 = (any == 0);

        int e = (bid - FILL_BASE) * 256 + tid;       // < E exactly
        int src, dst;
        if (is64) { src = ei32[2 * e]; dst = ei32[2 * (E_EDGES + e)]; }
        else      { src = ei32[e];     dst = ei32[E_EDGES + e];       }
        int pos = atomicAdd(&g_cnt[src], 1);
        if (pos < DEG_CAP) g_edst[src * DEG_CAP + pos] = dst;
    } else if (bid < MV_BASE) {
        // ---- split-K fp32 tiled GEMM: BM=64 BN=64 BK=16, 4x4 per thread ---
        // z-major layout: z0 blocks first (wave-1 resident => flag producers run)
        int pb   = bid - PROJ_BASE;
        int z    = pb / N_TILES;             // 0..KSPLIT-1
        int y    = (pb % N_TILES) / 48;      // matrix
        int rowt = pb % 48;
        const float* W; float* out;
        if      (y == 0) { W = Wq; out = g_q7; }
        else if (y == 1) { W = Wk; out = g_k7; }
        else             { W = Wv; out = g_v7; }

        __shared__ __align__(16) float xsT[16][68];  // [k][row], padded
        __shared__ __align__(16) float ws[16][64];   // [k][col]

        int tx = tid & 15;
        int ty = tid >> 4;
        int row0 = rowt * 64;
        int kbeg = z * (IN_DIM / KSPLIT);
        int kend = kbeg + (IN_DIM / KSPLIT);

        float acc[4][4] = {};

        for (int k0 = kbeg; k0 < kend; k0 += 16) {
            {
                int r  = tid >> 2;
                int kk = (tid & 3) * 4;
                float4 v = *(const float4*)&x[(row0 + r) * IN_DIM + k0 + kk];
                xsT[kk + 0][r] = v.x; xsT[kk + 1][r] = v.y;
                xsT[kk + 2][r] = v.z; xsT[kk + 3][r] = v.w;
            }
            {
                int kk = tid >> 4;
                int c4 = (tid & 15) * 4;
                *(float4*)&ws[kk][c4] =
                    *(const float4*)&W[(k0 + kk) * HD + COL0 + c4];
            }
            __syncthreads();
#pragma unroll
            for (int k = 0; k < 16; k++) {
                float4 a  = *(const float4*)&xsT[k][ty * 4];
                float4 bb = *(const float4*)&ws[k][tx * 4];
                float av[4]  = {a.x, a.y, a.z, a.w};
                float bv4[4] = {bb.x, bb.y, bb.z, bb.w};
#pragma unroll
                for (int i = 0; i < 4; i++)
#pragma unroll
                    for (int j = 0; j < 4; j++)
                        acc[i][j] += av[i] * bv4[j];
            }
            __syncthreads();
        }

        int tile = y * 48 + rowt;
        if (z == 0) {
            // first slice: plain vector store, then publish the tile
#pragma unroll
            for (int i = 0; i < 4; i++) {
                int r = row0 + ty * 4 + i;
                float4 v4 = {acc[i][0], acc[i][1], acc[i][2], acc[i][3]};
                *(float4*)&out[r * D + tx * 4] = v4;
            }
            __syncthreads();
            __threadfence();
            if (tid == 0) atomicExch(&g_tile_flag[tile], 1);
        } else {
            // other slices: wait for the base store, then accumulate
            if (tid == 0) {
                while (atomicAdd(&g_tile_flag[tile], 0) == 0) { __nanosleep(64); }
            }
            __syncthreads();
#pragma unroll
            for (int i = 0; i < 4; i++) {
                int r = row0 + ty * 4 + i;
#pragma unroll
                for (int j = 0; j < 4; j++)
                    atomicAdd(&out[r * D + tx * 4 + j], acc[i][j]);
            }
        }
    } else {
        // ---- mv: g_mv for 32 output columns; waits for colsum partials ----
        __shared__ float xs[IN_DIM];
        __shared__ float pp[256];
        int mb = bid - MV_BASE;              // 0..15
        if (tid == 0) {
            while (atomicAdd(&g_cs_done, 0) < CS_BLOCKS) { __nanosleep(64); }
        }
        __syncthreads();
        float s0 = 0.f, s1 = 0.f;
#pragma unroll 8
        for (int b = 0; b < CS_BLOCKS; b++) {
            s0 += g_xsump[b * IN_DIM + tid];
            s1 += g_xsump[b * IN_DIM + tid + 256];
        }
        xs[tid] = s0; xs[tid + 256] = s1;
        __syncthreads();
        // 8 k-segments of 64 per column; local col = tid & 31
        int j  = mb * 32 + (tid & 31);
        int k0 = (tid >> 5) * 64;
        float p = 0.f;
#pragma unroll 8
        for (int k = 0; k < 64; k++) p += xs[k0 + k] * Wv[(k0 + k) * HD + j];
        pp[tid] = p;
        __syncthreads();
        if (tid < 32) {
            float q = 0.f;
#pragma unroll
            for (int s = 0; s < 8; s++) q += pp[tid + 32 * s];
            g_mv[mb * 32 + tid] = q;
        }
    }
}

// ---------------- K2: node kernel (block per src node) ---------------------
// Phase A: half-warp per edge computes score (4 shfls).
// Phase C: channel-parallel branch-free weighted-V accumulate (no shuffles).
// Also self-cleans all inter-replay state.
__global__ void __launch_bounds__(128)
node_kernel(const float* __restrict__ bq,
            const float* __restrict__ bk,
            const float* __restrict__ bv,
            float* __restrict__ out) {
    int n = blockIdx.x;
    __shared__ __align__(16) float qs[64];      // q row + bq
    __shared__ __align__(16) float bks[64];
    __shared__ __align__(16) float bvs[64];
    __shared__ int   dlist[DEG_CAP];
    __shared__ float w[DEG_CAP];                // expm1 weights (0 for dups)
    __shared__ unsigned char keep[DEG_CAP];
    __shared__ float pacc[2][64];
    __shared__ float zs;
    __shared__ int   m_s;

    int tid  = threadIdx.x;          // 128 threads
    int lane = tid & 31;
    int wid  = tid >> 5;

    if (tid == 0) {
        int mm = g_cnt[n];
        g_cnt[n] = 0;                // self-clean for next graph replay
        m_s = (mm > DEG_CAP) ? DEG_CAP : mm;
        zs = 0.f;
        if (n < N_TILES) g_tile_flag[n] = 0;
        if (n == N_TILES) g_cs_done = 0;
    }
    if (tid < 64) {
        qs[tid]  = g_q7[n * D + tid] + bq[COL0 + tid];
        bks[tid] = bk[COL0 + tid];
        bvs[tid] = bv[COL0 + tid];
    }
    __syncthreads();
    int m = m_s;
    for (int i = tid; i < m; i += 128) dlist[i] = g_edst[n * DEG_CAP + i];
    __syncthreads();

    // dedupe flags (dense masked matrix holds each (src,dst) cell once)
    for (int i = tid; i < m; i += 128) {
        int d = dlist[i];
        unsigned char k = 1;
        for (int j = 0; j < i; j++)
            if (dlist[j] == d) { k = 0; break; }
        keep[i] = k;
    }

    // Phase A: half-warp (16 lanes) per edge; dup edges compute same w (zeroed later)
    {
        int hw = tid >> 4;                 // 0..7
        int hl = tid & 15;                 // 0..15
        unsigned hmask = 0xFFFFu << ((hw & 1) * 16);
        float4 q4  = ((const float4*)qs)[hl];
        float4 bk4 = ((const float4*)bks)[hl];
        for (int i = hw; i < m; i += 8) {
            int d = dlist[i];
            float4 k4 = ((const float4*)(g_k7 + d * D))[hl];
            float p = q4.x * (k4.x + bk4.x) + q4.y * (k4.y + bk4.y)
                    + q4.z * (k4.z + bk4.z) + q4.w * (k4.w + bk4.w);
#pragma unroll
            for (int o = 8; o; o >>= 1) p += __shfl_xor_sync(hmask, p, o);
            if (hl == 0) w[i] = expm1f(p * 0.125f);   // e^{s}-1, s = dot/8
        }
    }
    __syncthreads();

    // zero duplicate weights -> branch-free accumulate
    for (int i = tid; i < m; i += 128) if (!keep[i]) w[i] = 0.f;
    __syncthreads();

    // z = sum w (warp 0)
    if (wid == 0) {
        float zz = 0.f;
        for (int i = lane; i < m; i += 32) zz += w[i];
#pragma unroll
        for (int o = 16; o; o >>= 1) zz += __shfl_xor_sync(0xffffffffu, zz, o);
        if (lane == 0) zs = zz;
    }

    // Phase C: channel-parallel weighted-V accumulate (coalesced, high MLP)
    {
        int c = tid & 63;
        int g = tid >> 6;                  // 0 or 1
        float bvc = bvs[c];
        float a = 0.f;
        int i = g;
        for (; i + 8 <= m; i += 8) {       // 4-deep MLP per group
            a += w[i]     * (g_v7[dlist[i]     * D + c] + bvc);
            a += w[i + 2] * (g_v7[dlist[i + 2] * D + c] + bvc);
            a += w[i + 4] * (g_v7[dlist[i + 4] * D + c] + bvc);
            a += w[i + 6] * (g_v7[dlist[i + 6] * D + c] + bvc);
        }
        for (; i < m; i += 2)
            a += w[i] * (g_v7[dlist[i] * D + c] + bvc);
        pacc[g][c] = a;
    }
    __syncthreads();

    // head 7 output
    if (tid < 64) {
        float a  = pacc[0][tid] + pacc[1][tid];
        float vsum = g_mv[COL0 + tid] + (float)N_NODES * bvs[tid];
        out[n * HD + COL0 + tid] = (vsum + a) / ((float)N_NODES + zs);
    }
    // heads 0..6: uniform softmax -> broadcast mean of v
    for (int c = tid; c < COL0; c += 128)
        out[n * HD + c] = g_mv[c] * (1.f / N_NODES) + bv[c];
}

// ---------------------------------------------------------------------------
extern "C" void kernel_launch(void* const* d_in, const int* in_sizes, int n_in,
                              void* d_out, int out_size) {
    const float* x    = (const float*)d_in[0];
    const int*   ei32 = (const int*)d_in[1];     // int32 OR int64 (sniffed per block)
    const float* Wq   = (const float*)d_in[2];
    const float* Wk   = (const float*)d_in[3];
    const float* Wv   = (const float*)d_in[4];
    const float* bq   = (const float*)d_in[5];
    const float* bk   = (const float*)d_in[6];
    const float* bv   = (const float*)d_in[7];
    float* out = (float*)d_out;

    mega_kernel<<<MEGA_BLOCKS, 256>>>(x, ei32, Wq, Wk, Wv);
    node_kernel<<<N_NODES, 128>>>(bq, bk, bv, out);
}

// round 11
// speedup vs baseline: 1.0776x; 1.0776x over previous
#include <cuda_runtime.h>
#include <math.h>

// Problem constants (fixed by the dataset)
#define N_NODES 3072
#define IN_DIM  512
#define HD      512      // H*D
#define D       64
#define E_EDGES 98304
#define COL0    448      // start column of head 7 in the H*D projection
#define DEG_CAP 128      // fixed-stride adjacency slot count (Poisson(32): max~64)
#define KSPLIT  4        // split-K factor for proj

// mega grid layout (order matters for the spin-flag dependencies)
#define CS_BLOCKS   192              // colsum partials, 16 rows each
#define FILL_BLOCKS 384              // 384*256 = E exactly
#define PROJ_BLOCKS 576              // KSPLIT x 3 mats x 48 row-tiles (z-major)
#define MV_BLOCKS   16               // 32 cols each
#define CS_BASE     0
#define FILL_BASE   (CS_BASE + CS_BLOCKS)
#define PROJ_BASE   (FILL_BASE + FILL_BLOCKS)
#define MV_BASE     (PROJ_BASE + PROJ_BLOCKS)
#define MEGA_BLOCKS (MV_BASE + MV_BLOCKS)
#define N_TILES     144              // 3 mats x 48 row-tiles

// node launch layout: head-7 blocks + broadcast-writer blocks
#define BC_F4_TOTAL (N_NODES * (COL0 / 4))   // 344064 float4 stores
#define BC_BLOCKS   (BC_F4_TOTAL / 256)      // 1344 blocks x 256 f4 (128thr x 2)
#define NODE_GRID   (N_NODES + BC_BLOCKS)

// ---------------- scratch (device globals: allocation-free, zero-init) -----
__device__ float g_q7[N_NODES * D];        // raw x@Wq[:,448:512] (no bias)
__device__ float g_k7[N_NODES * D];
__device__ float g_v7[N_NODES * D];
__device__ int   g_cnt[N_NODES];           // self-cleaned by node_kernel
__device__ int   g_edst[N_NODES * DEG_CAP];
__device__ float g_xsump[CS_BLOCKS * IN_DIM];  // colsum partials (plain stores)
__device__ __align__(16) float g_bc[COL0]; // broadcast row: mv/N + bv  (cols 0..447)
__device__ float g_vsum7[D];               // sum_m v7[m,d] incl. bias (cols 448..511)
__device__ int   g_tile_flag[N_TILES];     // z0-slice-done flags (self-cleaned)
__device__ int   g_cs_done;                // colsum-done counter (self-cleaned)

// ---------------- K1: mega kernel (colsum + fill + proj + mv) --------------
__global__ void __launch_bounds__(256)
mega_kernel(const float* __restrict__ x,
            const int*   __restrict__ ei32,
            const float* __restrict__ Wq,
            const float* __restrict__ Wk,
            const float* __restrict__ Wv,
            const float* __restrict__ bv) {
    int bid = blockIdx.x;
    int tid = threadIdx.x;

    if (bid < FILL_BASE) {
        // ---- colsum partials: 192 blocks x 16 rows, plain stores ----------
        int r0 = bid * 16;
        float s0 = 0.f, s1 = 0.f;
#pragma unroll
        for (int r = 0; r < 16; r++) {
            s0 += x[(r0 + r) * IN_DIM + tid];
            s1 += x[(r0 + r) * IN_DIM + tid + 256];
        }
        g_xsump[bid * IN_DIM + tid]       = s0;
        g_xsump[bid * IN_DIM + tid + 256] = s1;
        __syncthreads();
        __threadfence();
        if (tid == 0) atomicAdd(&g_cs_done, 1);
    } else if (bid < PROJ_BASE) {
        // ---- edge fill with per-block dtype sniff -------------------------
        // int64 layout => odd int32 words are high halves of ids < 3072 => 0.
        // int32 layout => odd words are random node ids (P(all 0) ~ 3072^-128).
        int flag = (tid < 128) ? ei32[2 * tid + 1] : 0;
        int any  = __syncthreads_or(flag);
        int is64 = (any == 0);

        int e = (bid - FILL_BASE) * 256 + tid;       // < E exactly
        int src, dst;
        if (is64) { src = ei32[2 * e]; dst = ei32[2 * (E_EDGES + e)]; }
        else      { src = ei32[e];     dst = ei32[E_EDGES + e];       }
        int pos = atomicAdd(&g_cnt[src], 1);
        if (pos < DEG_CAP) g_edst[src * DEG_CAP + pos] = dst;
    } else if (bid < MV_BASE) {
        // ---- split-K fp32 tiled GEMM: BM=64 BN=64 BK=16, 4x4 per thread ---
        int pb   = bid - PROJ_BASE;
        int z    = pb / N_TILES;             // 0..KSPLIT-1 (z0 first in grid)
        int y    = (pb % N_TILES) / 48;      // matrix
        int rowt = pb % 48;
        const float* W; float* out;
        if      (y == 0) { W = Wq; out = g_q7; }
        else if (y == 1) { W = Wk; out = g_k7; }
        else             { W = Wv; out = g_v7; }

        __shared__ __align__(16) float xsT[16][68];  // [k][row], padded
        __shared__ __align__(16) float ws[16][64];   // [k][col]

        int tx = tid & 15;
        int ty = tid >> 4;
        int row0 = rowt * 64;
        int kbeg = z * (IN_DIM / KSPLIT);
        int kend = kbeg + (IN_DIM / KSPLIT);

        float acc[4][4] = {};

        for (int k0 = kbeg; k0 < kend; k0 += 16) {
            {
                int r  = tid >> 2;
                int kk = (tid & 3) * 4;
                float4 v = *(const float4*)&x[(row0 + r) * IN_DIM + k0 + kk];
                xsT[kk + 0][r] = v.x; xsT[kk + 1][r] = v.y;
                xsT[kk + 2][r] = v.z; xsT[kk + 3][r] = v.w;
            }
            {
                int kk = tid >> 4;
                int c4 = (tid & 15) * 4;
                *(float4*)&ws[kk][c4] =
                    *(const float4*)&W[(k0 + kk) * HD + COL0 + c4];
            }
            __syncthreads();
#pragma unroll
            for (int k = 0; k < 16; k++) {
                float4 a  = *(const float4*)&xsT[k][ty * 4];
                float4 bb = *(const float4*)&ws[k][tx * 4];
                float av[4]  = {a.x, a.y, a.z, a.w};
                float bv4[4] = {bb.x, bb.y, bb.z, bb.w};
#pragma unroll
                for (int i = 0; i < 4; i++)
#pragma unroll
                    for (int j = 0; j < 4; j++)
                        acc[i][j] += av[i] * bv4[j];
            }
            __syncthreads();
        }

        int tile = y * 48 + rowt;
        if (z == 0) {
#pragma unroll
            for (int i = 0; i < 4; i++) {
                int r = row0 + ty * 4 + i;
                float4 v4 = {acc[i][0], acc[i][1], acc[i][2], acc[i][3]};
                *(float4*)&out[r * D + tx * 4] = v4;
            }
            __syncthreads();
            __threadfence();
            if (tid == 0) atomicExch(&g_tile_flag[tile], 1);
        } else {
            if (tid == 0) {
                while (atomicAdd(&g_tile_flag[tile], 0) == 0) { __nanosleep(64); }
            }
            __syncthreads();
#pragma unroll
            for (int i = 0; i < 4; i++) {
                int r = row0 + ty * 4 + i;
#pragma unroll
                for (int j = 0; j < 4; j++)
                    atomicAdd(&out[r * D + tx * 4 + j], acc[i][j]);
            }
        }
    } else {
        // ---- mv: derived broadcast/vsum values for 32 output columns ------
        __shared__ float xs[IN_DIM];
        __shared__ float pp[256];
        int mb = bid - MV_BASE;              // 0..15
        if (tid == 0) {
            while (atomicAdd(&g_cs_done, 0) < CS_BLOCKS) { __nanosleep(64); }
        }
        __syncthreads();
        float s0 = 0.f, s1 = 0.f;
#pragma unroll 8
        for (int b = 0; b < CS_BLOCKS; b++) {
            s0 += g_xsump[b * IN_DIM + tid];
            s1 += g_xsump[b * IN_DIM + tid + 256];
        }
        xs[tid] = s0; xs[tid + 256] = s1;
        __syncthreads();
        int j  = mb * 32 + (tid & 31);
        int k0 = (tid >> 5) * 64;
        float p = 0.f;
#pragma unroll 8
        for (int k = 0; k < 64; k++) p += xs[k0 + k] * Wv[(k0 + k) * HD + j];
        pp[tid] = p;
        __syncthreads();
        if (tid < 32) {
            float q = 0.f;
#pragma unroll
            for (int s = 0; s < 8; s++) q += pp[tid + 32 * s];
            int jj = mb * 32 + tid;
            if (jj < COL0) g_bc[jj] = q * (1.f / N_NODES) + bv[jj];
            else           g_vsum7[jj - COL0] = q + (float)N_NODES * bv[jj];
        }
    }
}

// ---------------- K2: node kernel + broadcast writers ----------------------
// node blocks (bid < N_NODES): head-7 only; bitmap dedupe; self-clean state.
// BC blocks (bid >= N_NODES): float4-copy the broadcast row into cols 0..447.
__global__ void __launch_bounds__(128)
node_kernel(const float* __restrict__ bq,
            const float* __restrict__ bk,
            const float* __restrict__ bv,
            float* __restrict__ out) {
    int tid = threadIdx.x;

    if (blockIdx.x >= N_NODES) {
        // ---- broadcast writer: 256 float4 per block (2 per thread) --------
        int base = (blockIdx.x - N_NODES) * 256;
#pragma unroll
        for (int k = 0; k < 2; k++) {
            int idx = base + k * 128 + tid;          // < 344064
            int n   = idx / (COL0 / 4);
            int c4  = idx - n * (COL0 / 4);
            float4 v = *(const float4*)&g_bc[c4 * 4];
            *(float4*)&out[n * HD + c4 * 4] = v;
        }
        return;
    }

    int n = blockIdx.x;
    __shared__ __align__(16) float qs[64];      // q row + bq
    __shared__ __align__(16) float bks[64];
    __shared__ __align__(16) float bvs[64];
    __shared__ int   dlist[DEG_CAP];
    __shared__ float w[DEG_CAP];                // expm1 weights (0 for dups)
    __shared__ unsigned char keep[DEG_CAP];
    __shared__ unsigned bm[N_NODES / 32];       // 96-word dst bitmap
    __shared__ float pacc[2][64];
    __shared__ float zs;
    __shared__ int   m_s;

    int lane = tid & 31;
    int wid  = tid >> 5;

    if (tid == 0) {
        int mm = g_cnt[n];
        g_cnt[n] = 0;                // self-clean for next graph replay
        m_s = (mm > DEG_CAP) ? DEG_CAP : mm;
        zs = 0.f;
        if (n < N_TILES) g_tile_flag[n] = 0;
        if (n == N_TILES) g_cs_done = 0;
    }
    if (tid < 64) {
        qs[tid]  = g_q7[n * D + tid] + bq[COL0 + tid];
        bks[tid] = bk[COL0 + tid];
        bvs[tid] = bv[COL0 + tid];
    }
    if (tid < N_NODES / 32) bm[tid] = 0u;
    __syncthreads();
    int m = m_s;
    for (int i = tid; i < m; i += 128) dlist[i] = g_edst[n * DEG_CAP + i];
    __syncthreads();

    // dedupe via smem bitmap: first atomicOr setter keeps the edge.
    // (dup edges have identical scores, so any single survivor is exact.)
    for (int i = tid; i < m; i += 128) {
        int d = dlist[i];
        unsigned mask = 1u << (d & 31);
        unsigned old  = atomicOr(&bm[d >> 5], mask);
        keep[i] = (old & mask) ? 0 : 1;
    }

    // Phase A: half-warp (16 lanes) per edge; dup edges compute same w (zeroed later)
    {
        int hw = tid >> 4;                 // 0..7
        int hl = tid & 15;                 // 0..15
        unsigned hmask = 0xFFFFu << ((hw & 1) * 16);
        float4 q4  = ((const float4*)qs)[hl];
        float4 bk4 = ((const float4*)bks)[hl];
        for (int i = hw; i < m; i += 8) {
            int d = dlist[i];
            float4 k4 = ((const float4*)(g_k7 + d * D))[hl];
            float p = q4.x * (k4.x + bk4.x) + q4.y * (k4.y + bk4.y)
                    + q4.z * (k4.z + bk4.z) + q4.w * (k4.w + bk4.w);
#pragma unroll
            for (int o = 8; o; o >>= 1) p += __shfl_xor_sync(hmask, p, o);
            if (hl == 0) w[i] = expm1f(p * 0.125f);   // e^{s}-1, s = dot/8
        }
    }
    __syncthreads();

    // zero duplicate weights -> branch-free accumulate
    for (int i = tid; i < m; i += 128) if (!keep[i]) w[i] = 0.f;
    __syncthreads();

    // z = sum w (warp 0)
    if (wid == 0) {
        float zz = 0.f;
        for (int i = lane; i < m; i += 32) zz += w[i];
#pragma unroll
        for (int o = 16; o; o >>= 1) zz += __shfl_xor_sync(0xffffffffu, zz, o);
        if (lane == 0) zs = zz;
    }

    // Phase C: channel-parallel weighted-V accumulate (coalesced, high MLP)
    {
        int c = tid & 63;
        int g = tid >> 6;                  // 0 or 1
        float bvc = bvs[c];
        float a = 0.f;
        int i = g;
        for (; i + 8 <= m; i += 8) {       // 4-deep MLP per group
            a += w[i]     * (g_v7[dlist[i]     * D + c] + bvc);
            a += w[i + 2] * (g_v7[dlist[i + 2] * D + c] + bvc);
            a += w[i + 4] * (g_v7[dlist[i + 4] * D + c] + bvc);
            a += w[i + 6] * (g_v7[dlist[i + 6] * D + c] + bvc);
        }
        for (; i < m; i += 2)
            a += w[i] * (g_v7[dlist[i] * D + c] + bvc);
        pacc[g][c] = a;
    }
    __syncthreads();

    // head 7 output only (broadcast cols handled by BC blocks)
    if (tid < 64) {
        float a = pacc[0][tid] + pacc[1][tid];
        out[n * HD + COL0 + tid] =
            (g_vsum7[tid] + a) / ((float)N_NODES + zs);
    }
}

// ---------------------------------------------------------------------------
extern "C" void kernel_launch(void* const* d_in, const int* in_sizes, int n_in,
                              void* d_out, int out_size) {
    const float* x    = (const float*)d_in[0];
    const int*   ei32 = (const int*)d_in[1];     // int32 OR int64 (sniffed per block)
    const float* Wq   = (const float*)d_in[2];
    const float* Wk   = (const float*)d_in[3];
    const float* Wv   = (const float*)d_in[4];
    const float* bq   = (const float*)d_in[5];
    const float* bk   = (const float*)d_in[6];
    const float* bv   = (const float*)d_in[7];
    float* out = (float*)d_out;

    mega_kernel<<<MEGA_BLOCKS, 256>>>(x, ei32, Wq, Wk, Wv, bv);
    node_kernel<<<NODE_GRID, 128>>>(bq, bk, bv, out);
}